// round 11
// baseline (speedup 1.0000x reference)
#include <cuda_runtime.h>
#include <cuda.h>
#include <cuda_fp16.h>
#include <cstdint>

// ---------------- problem constants ----------------
#define BDIM 4096
#define HDIM 2048
#define KTOT 4096            // K = IN + H
#define NTOT 8192            // 4 gates * H
#define TILE_M 128           // batch rows per CTA
#define TILE_N 128           // n' cols per CTA (32 j * 4 gates)
#define KC 64                // K per mainloop iter (64 fp16 = 128B row)
#define STAGES 3
#define ITERS (KTOT / KC)    // 64
#define A_BYTES (TILE_M * KC * 2)      // 16384
#define B_BYTES (TILE_N * KC * 2)      // 16384
#define STAGE_BYTES (A_BYTES + B_BYTES) // 32768
#define SMEM_BYTES (2048 + 1024 + STAGES * STAGE_BYTES)  // 101376 -> 2 CTAs/SM

// ---------------- scratch (static device memory; no allocations) ----------------
__device__ __align__(1024) __half g_A[(size_t)BDIM * KTOT];  // 32 MB [b, k] k-fast
__device__ __align__(1024) __half g_W[(size_t)NTOT * KTOT];  // 64 MB [n'=4j+g, k] k-fast

// ---------------- PTX helpers ----------------
static __device__ __forceinline__ uint32_t smem_u32(const void* p) {
    uint32_t a;
    asm("{ .reg .u64 t; cvta.to.shared.u64 t, %1; cvt.u32.u64 %0, t; }" : "=r"(a) : "l"(p));
    return a;
}
static __device__ __forceinline__ void mbar_init(uint32_t a, uint32_t cnt) {
    asm volatile("mbarrier.init.shared.b64 [%0], %1;" :: "r"(a), "r"(cnt) : "memory");
}
static __device__ __forceinline__ void mbar_expect(uint32_t a, uint32_t bytes) {
    asm volatile("mbarrier.arrive.expect_tx.shared.b64 _, [%0], %1;" :: "r"(a), "r"(bytes) : "memory");
}
static __device__ __forceinline__ void mbar_arrive(uint32_t a) {
    asm volatile("mbarrier.arrive.shared.b64 _, [%0];" :: "r"(a) : "memory");
}
static __device__ __forceinline__ void mbar_wait(uint32_t a, uint32_t parity) {
    asm volatile(
        "{\n\t"
        ".reg .pred P;\n\t"
        "LAB_WAIT_%=:\n\t"
        "mbarrier.try_wait.parity.acquire.cta.shared::cta.b64 P, [%0], %1, 0x989680;\n\t"
        "@P bra.uni LAB_DONE_%=;\n\t"
        "bra.uni LAB_WAIT_%=;\n\t"
        "LAB_DONE_%=:\n\t"
        "}"
        :: "r"(a), "r"(parity) : "memory");
}
static __device__ __forceinline__ void tma2d(uint32_t smem_dst, const void* map, int cx, int cy, uint32_t bar) {
    asm volatile(
        "cp.async.bulk.tensor.2d.shared::cta.global.tile.mbarrier::complete_tx::bytes "
        "[%0], [%1, {%2, %3}], [%4];"
        :: "r"(smem_dst), "l"(map), "r"(cx), "r"(cy), "r"(bar) : "memory");
}
static __device__ __forceinline__ void ldsm_x4(uint32_t* r, uint32_t addr) {
    asm volatile("ldmatrix.sync.aligned.m8n8.x4.shared.b16 {%0,%1,%2,%3}, [%4];"
                 : "=r"(r[0]), "=r"(r[1]), "=r"(r[2]), "=r"(r[3]) : "r"(addr));
}
// fp16-accumulator HMMA: D,C are 2 x b32 (4 halves), same coord layout as f32 acc
static __device__ __forceinline__ void mma_f16acc(uint32_t& d0, uint32_t& d1,
                                                  uint32_t a0, uint32_t a1, uint32_t a2, uint32_t a3,
                                                  uint32_t b0, uint32_t b1,
                                                  uint32_t c0, uint32_t c1) {
    asm volatile(
        "mma.sync.aligned.m16n8k16.row.col.f16.f16.f16.f16 "
        "{%0,%1}, {%2,%3,%4,%5}, {%6,%7}, {%8,%9};"
        : "=r"(d0), "=r"(d1)
        : "r"(a0), "r"(a1), "r"(a2), "r"(a3), "r"(b0), "r"(b1), "r"(c0), "r"(c1));
}
static __device__ __forceinline__ float sigf(float x) {
    x = fminf(fmaxf(x, -30.0f), 30.0f);
    return __fdividef(1.0f, 1.0f + __expf(-x));
}
static __device__ __forceinline__ float tanhfast(float x) {
    x = fminf(fmaxf(x, -15.0f), 15.0f);
    float e = __expf(-2.0f * x);
    return __fdividef(1.0f - e, 1.0f + e);
}

// ---------------- prepack kernels (plain k-contiguous layouts) ----------------
__global__ void pack_A(const float* __restrict__ x, const float* __restrict__ h) {
    size_t i8 = (size_t)blockIdx.x * blockDim.x + threadIdx.x;
    size_t idx = i8 * 8;                 // 8 fp16 per thread (16B store)
    int bb = (int)(idx >> 12);
    int k0 = (int)(idx & 4095);
    const float* src = (k0 < HDIM) ? (x + (size_t)bb * HDIM + k0)
                                   : (h + (size_t)bb * HDIM + (k0 - HDIM));
    float4 f0 = *(const float4*)(src);
    float4 f1 = *(const float4*)(src + 4);
    __half2 h0 = __floats2half2_rn(f0.x, f0.y);
    __half2 h1 = __floats2half2_rn(f0.z, f0.w);
    __half2 h2 = __floats2half2_rn(f1.x, f1.y);
    __half2 h3 = __floats2half2_rn(f1.z, f1.w);
    *(uint4*)(g_A + idx) = make_uint4(*(uint32_t*)&h0, *(uint32_t*)&h1,
                                      *(uint32_t*)&h2, *(uint32_t*)&h3);
}

// transpose w_g[k, j] (j-fast) -> g_W[n'=4j+g, k] (k-fast), fp16
__global__ void pack_W(const float* __restrict__ w0, const float* __restrict__ w1,
                       const float* __restrict__ w2, const float* __restrict__ w3,
                       const float* __restrict__ w4, const float* __restrict__ w5,
                       const float* __restrict__ w6, const float* __restrict__ w7) {
    int z = blockIdx.z;          // 0..7: z = p*4 + g  (p: 0=x-part, 1=h-part)
    int g = z & 3;
    int p = z >> 2;
    const float* src;
    switch (z) {
        case 0: src = w0; break; case 1: src = w1; break;
        case 2: src = w2; break; case 3: src = w3; break;
        case 4: src = w4; break; case 5: src = w5; break;
        case 6: src = w6; break; default: src = w7; break;
    }
    __shared__ float t[32][33];
    int tx = threadIdx.x, ty = threadIdx.y;  // (32, 8)
    int k0 = blockIdx.x * 32, j0 = blockIdx.y * 32;
#pragma unroll
    for (int rr = 0; rr < 4; rr++) {
        int kk = ty + rr * 8;
        t[kk][tx] = src[(size_t)(k0 + kk) * HDIM + j0 + tx];
    }
    __syncthreads();
#pragma unroll
    for (int rr = 0; rr < 4; rr++) {
        int jj = ty + rr * 8;
        int np = (j0 + jj) * 4 + g;
        g_W[(size_t)np * KTOT + p * HDIM + k0 + tx] = __float2half_rn(t[tx][jj]);
    }
}

// ---------------- fused GEMM + LSTM-cell kernel (fp16-acc HMMA chains) ----------------
__global__ void __launch_bounds__(256, 2) lstm_gemm(
    const __grid_constant__ CUtensorMap mapA,
    const __grid_constant__ CUtensorMap mapW,
    const float* __restrict__ cin,
    const float* __restrict__ bi, const float* __restrict__ bf,
    const float* __restrict__ bo, const float* __restrict__ bg,
    float* __restrict__ out) {
    extern __shared__ char smem[];
    const uint32_t base = smem_u32(smem);
    const int tid = threadIdx.x;
    const int lane = tid & 31, w = tid >> 5;
    const int wm = (w >> 2) * 64;        // warp M offset (2 warps in M, 64 rows each)
    const int wn = (w & 3) * 32;         // warp N offset (4 warps in N, 32 cols each)

    // CTA swizzle: groups of 8 M-tiles x 64 N-tiles (512 CTAs) keep wave footprint in L2
    int bid = blockIdx.x;
    int grp = bid >> 9, rem = bid & 511;
    int m_t = (grp << 3) + (rem & 7);    // 0..31
    int n_t = rem >> 3;                  // 0..63
    const int y0 = m_t * TILE_M, x0 = n_t * TILE_N;

    const uint32_t FULLB = base;         // 3 x 8B
    const uint32_t EMPTB = base + 32;    // 3 x 8B
    float* bias_s = (float*)(smem + 64); // 128 floats
    const uint32_t t0 = (base + 2048 + 1023) & ~1023u;

    if (tid == 0) {
        for (int st = 0; st < STAGES; st++) {
            mbar_init(FULLB + 8 * st, 1);
            mbar_init(EMPTB + 8 * st, 8);
        }
    }
    if (tid < 128) {
        const float* bp[4] = {bi, bf, bo, bg};
        bias_s[tid] = bp[tid & 3][n_t * 32 + (tid >> 2)];
    }
    __syncthreads();

    if (tid == 0) {
        for (int st = 0; st < STAGES; st++) {
            mbar_expect(FULLB + 8 * st, STAGE_BYTES);
            tma2d(t0 + st * STAGE_BYTES, &mapA, st * KC, y0, FULLB + 8 * st);
            tma2d(t0 + st * STAGE_BYTES + A_BYTES, &mapW, st * KC, x0, FULLB + 8 * st);
        }
    }

    float acc[4][4][4];
#pragma unroll
    for (int mt = 0; mt < 4; mt++)
#pragma unroll
        for (int nt = 0; nt < 4; nt++)
#pragma unroll
            for (int q = 0; q < 4; q++) acc[mt][nt][q] = 0.0f;

    // ldmatrix per-lane addressing: mi = matrix index (lane>>3), rr = row (lane&7)
    const int rr = lane & 7, mi = lane >> 3;
    const uint32_t xr = (uint32_t)(rr << 4);
    const uint32_t a_row = (uint32_t)(wm + ((mi & 1) << 3) + rr) * 128;
    const uint32_t b_row = (uint32_t)(wn + ((mi >> 1) << 3) + rr) * 128;
    const uint32_t a_cb = ((uint32_t)((mi >> 1) << 4)) ^ xr;
    const uint32_t b_cb = ((uint32_t)((mi & 1) << 4)) ^ xr;

    int s = 0, ph = 0;
    for (int i = 0; i < ITERS; i++) {
        mbar_wait(FULLB + 8 * s, ph);
        uint32_t sa = t0 + s * STAGE_BYTES;
        uint32_t sb = sa + A_BYTES;
        uint32_t acch[4][4][2];          // per-iter fp16 chain accumulators (k-span 64)
#pragma unroll
        for (int g = 0; g < 4; g++) {
            uint32_t af[4][4];
#pragma unroll
            for (int mt = 0; mt < 4; mt++)
                ldsm_x4(af[mt], sa + a_row + mt * 2048 + (a_cb ^ (uint32_t)(g * 32)));
            uint32_t bf_[2][4];
#pragma unroll
            for (int p = 0; p < 2; p++)
                ldsm_x4(bf_[p], sb + b_row + p * 2048 + (b_cb ^ (uint32_t)(g * 32)));
#pragma unroll
            for (int mt = 0; mt < 4; mt++)
#pragma unroll
                for (int nt = 0; nt < 4; nt++) {
                    uint32_t c0 = (g == 0) ? 0u : acch[mt][nt][0];
                    uint32_t c1 = (g == 0) ? 0u : acch[mt][nt][1];
                    mma_f16acc(acch[mt][nt][0], acch[mt][nt][1],
                               af[mt][0], af[mt][1], af[mt][2], af[mt][3],
                               bf_[nt >> 1][(nt & 1) * 2], bf_[nt >> 1][(nt & 1) * 2 + 1],
                               c0, c1);
                }
        }
        // promote fp16 span sums into persistent f32 accumulators
#pragma unroll
        for (int mt = 0; mt < 4; mt++)
#pragma unroll
            for (int nt = 0; nt < 4; nt++) {
                float2 f0 = __half22float2(*(__half2*)&acch[mt][nt][0]);
                float2 f1 = __half22float2(*(__half2*)&acch[mt][nt][1]);
                acc[mt][nt][0] += f0.x;
                acc[mt][nt][1] += f0.y;
                acc[mt][nt][2] += f1.x;
                acc[mt][nt][3] += f1.y;
            }
        if (lane == 0) mbar_arrive(EMPTB + 8 * s);
        if (tid == 0 && i + STAGES < ITERS) {
            mbar_wait(EMPTB + 8 * s, ph);
            mbar_expect(FULLB + 8 * s, STAGE_BYTES);
            tma2d(t0 + s * STAGE_BYTES, &mapA, (i + STAGES) * KC, y0, FULLB + 8 * s);
            tma2d(t0 + s * STAGE_BYTES + A_BYTES, &mapW, (i + STAGES) * KC, x0, FULLB + 8 * s);
        }
        if (++s == STAGES) { s = 0; ph ^= 1; }
    }

    // ---------- fused LSTM-cell epilogue ----------
    // thread owns C cols (2c, 2c+1), c = lane&3; gate pair (i,f) on even c, (o,g) on odd c.
    // shfl_xor(1) pairs them; even lane stores h_t, odd lane stores c_t.
    const size_t CELL = (size_t)BDIM * HDIM;
    const int arow = lane >> 2;
#pragma unroll
    for (int mt = 0; mt < 4; mt++) {
#pragma unroll
        for (int nt = 0; nt < 4; nt++) {
            int nloc = wn + nt * 8;
            float bb0 = bias_s[nloc + 2 * (lane & 3)];
            float bb1 = bias_s[nloc + 2 * (lane & 3) + 1];
            int jg = n_t * 32 + (nloc >> 2) + ((lane & 2) >> 1);
#pragma unroll
            for (int hh = 0; hh < 2; hh++) {
                float v0 = acc[mt][nt][hh * 2 + 0] + bb0;
                float v1 = acc[mt][nt][hh * 2 + 1] + bb1;
                float u0 = __shfl_xor_sync(0xffffffffu, v0, 1);
                float u1 = __shfl_xor_sync(0xffffffffu, v1, 1);
                float iv, fv, ov, gv;
                if ((lane & 1) == 0) { iv = v0; fv = v1; ov = u0; gv = u1; }
                else                 { iv = u0; fv = u1; ov = v0; gv = v1; }
                int brow = y0 + wm + mt * 16 + arow + hh * 8;
                size_t off = (size_t)brow * HDIM + jg;
                float cv = __ldg(cin + off);
                float is = sigf(iv), fs = sigf(fv), gt = tanhfast(gv);
                float ct = cv * fs + is * gt;
                if ((lane & 1) == 0) out[off] = sigf(ov) * tanhfast(ct);
                else                 out[CELL + off] = ct;
            }
        }
    }
}

// ---------------- host launch ----------------
typedef CUresult (CUDAAPI* EncFn)(CUtensorMap*, CUtensorMapDataType, cuuint32_t, void*,
                                  const cuuint64_t*, const cuuint64_t*, const cuuint32_t*,
                                  const cuuint32_t*, CUtensorMapInterleave, CUtensorMapSwizzle,
                                  CUtensorMapL2promotion, CUtensorMapFloatOOBfill);

extern "C" void kernel_launch(void* const* d_in, const int* in_sizes, int n_in,
                              void* d_out, int out_size) {
    const float* x = (const float*)d_in[0];
    const float* h = (const float*)d_in[1];
    const float* c = (const float*)d_in[2];
    const float* wx[4] = {(const float*)d_in[3], (const float*)d_in[4],
                          (const float*)d_in[5], (const float*)d_in[6]};
    const float* wh[4] = {(const float*)d_in[7], (const float*)d_in[8],
                          (const float*)d_in[9], (const float*)d_in[10]};
    const float* bi = (const float*)d_in[11];
    const float* bf = (const float*)d_in[12];
    const float* bo = (const float*)d_in[13];
    const float* bg = (const float*)d_in[14];

    void* pA = nullptr; void* pW = nullptr;
    cudaGetSymbolAddress(&pA, g_A);
    cudaGetSymbolAddress(&pW, g_W);

    EncFn enc = nullptr;
    cudaDriverEntryPointQueryResult qres;
    cudaGetDriverEntryPoint("cuTensorMapEncodeTiled", (void**)&enc, cudaEnableDefault, &qres);

    CUtensorMap mA, mW;
    {
        cuuint64_t dims[2] = {KTOT, BDIM};
        cuuint64_t st[1] = {KTOT * sizeof(__half)};
        cuuint32_t box[2] = {KC, TILE_M};
        cuuint32_t es[2] = {1, 1};
        enc(&mA, CU_TENSOR_MAP_DATA_TYPE_FLOAT16, 2, pA, dims, st, box, es,
            CU_TENSOR_MAP_INTERLEAVE_NONE, CU_TENSOR_MAP_SWIZZLE_128B,
            CU_TENSOR_MAP_L2_PROMOTION_L2_128B, CU_TENSOR_MAP_FLOAT_OOB_FILL_NONE);
    }
    {
        cuuint64_t dims[2] = {KTOT, NTOT};
        cuuint64_t st[1] = {KTOT * sizeof(__half)};
        cuuint32_t box[2] = {KC, TILE_N};
        cuuint32_t es[2] = {1, 1};
        enc(&mW, CU_TENSOR_MAP_DATA_TYPE_FLOAT16, 2, pW, dims, st, box, es,
            CU_TENSOR_MAP_INTERLEAVE_NONE, CU_TENSOR_MAP_SWIZZLE_128B,
            CU_TENSOR_MAP_L2_PROMOTION_L2_128B, CU_TENSOR_MAP_FLOAT_OOB_FILL_NONE);
    }

    pack_A<<<(BDIM * KTOT) / 8 / 256, 256>>>(x, h);
    pack_W<<<dim3(HDIM / 32, HDIM / 32, 8), dim3(32, 8)>>>(
        wx[0], wx[1], wx[2], wx[3], wh[0], wh[1], wh[2], wh[3]);

    cudaFuncSetAttribute(lstm_gemm, cudaFuncAttributeMaxDynamicSharedMemorySize, SMEM_BYTES);
    lstm_gemm<<<(BDIM / TILE_M) * (NTOT / TILE_N), 256, SMEM_BYTES>>>(
        mA, mW, c, bi, bf, bo, bg, (float*)d_out);
}

// round 12
// speedup vs baseline: 1.1717x; 1.1717x over previous
#include <cuda_runtime.h>
#include <cuda.h>
#include <cuda_fp16.h>
#include <cstdint>

// ---------------- problem constants ----------------
#define BDIM 4096
#define HDIM 2048
#define KTOT 4096            // K = IN + H
#define NTOT 8192            // 4 gates * H
#define TILE_M 128           // batch rows per CTA
#define TILE_N 128           // n' cols per CTA (32 j * 4 gates)
#define KC 64                // K per mainloop iter (64 fp16 = 128B row)
#define STAGES 3
#define ITERS (KTOT / KC)    // 64
#define A_BYTES (TILE_M * KC * 2)      // 16384
#define B_BYTES (TILE_N * KC * 2)      // 16384
#define STAGE_BYTES (A_BYTES + B_BYTES) // 32768
#define SMEM_BYTES (2048 + 1024 + STAGES * STAGE_BYTES)  // 101376 -> 2 CTAs/SM

// fused-pack grid split
#define PACKA_BLOCKS ((BDIM * KTOT) / 8 / 256)   // 8192
#define PACKW_BLOCKS_PER_Z ((HDIM / 32) * (HDIM / 32))  // 4096
#define PACK_BLOCKS (PACKA_BLOCKS + 8 * PACKW_BLOCKS_PER_Z)  // 40960

// ---------------- scratch (static device memory; no allocations) ----------------
__device__ __align__(1024) __half g_A[(size_t)BDIM * KTOT];  // 32 MB [b, k] k-fast
__device__ __align__(1024) __half g_W[(size_t)NTOT * KTOT];  // 64 MB [n'=4j+g, k] k-fast

// ---------------- PTX helpers ----------------
static __device__ __forceinline__ uint32_t smem_u32(const void* p) {
    uint32_t a;
    asm("{ .reg .u64 t; cvta.to.shared.u64 t, %1; cvt.u32.u64 %0, t; }" : "=r"(a) : "l"(p));
    return a;
}
static __device__ __forceinline__ void mbar_init(uint32_t a, uint32_t cnt) {
    asm volatile("mbarrier.init.shared.b64 [%0], %1;" :: "r"(a), "r"(cnt) : "memory");
}
static __device__ __forceinline__ void mbar_expect(uint32_t a, uint32_t bytes) {
    asm volatile("mbarrier.arrive.expect_tx.shared.b64 _, [%0], %1;" :: "r"(a), "r"(bytes) : "memory");
}
static __device__ __forceinline__ void mbar_arrive(uint32_t a) {
    asm volatile("mbarrier.arrive.shared.b64 _, [%0];" :: "r"(a) : "memory");
}
// acquire wait — consumers (generic smem reads follow)
static __device__ __forceinline__ void mbar_wait(uint32_t a, uint32_t parity) {
    asm volatile(
        "{\n\t"
        ".reg .pred P;\n\t"
        "LAB_WAIT_%=:\n\t"
        "mbarrier.try_wait.parity.acquire.cta.shared::cta.b64 P, [%0], %1, 0x989680;\n\t"
        "@P bra.uni LAB_DONE_%=;\n\t"
        "bra.uni LAB_WAIT_%=;\n\t"
        "LAB_DONE_%=:\n\t"
        "}"
        :: "r"(a), "r"(parity) : "memory");
}
// relaxed wait — producer only (post-wait accesses are TMA async proxy)
static __device__ __forceinline__ void mbar_wait_relaxed(uint32_t a, uint32_t parity) {
    asm volatile(
        "{\n\t"
        ".reg .pred P;\n\t"
        "LAB_WAIT_%=:\n\t"
        "mbarrier.try_wait.parity.relaxed.cta.shared::cta.b64 P, [%0], %1, 0x989680;\n\t"
        "@P bra.uni LAB_DONE_%=;\n\t"
        "bra.uni LAB_WAIT_%=;\n\t"
        "LAB_DONE_%=:\n\t"
        "}"
        :: "r"(a), "r"(parity) : "memory");
}
static __device__ __forceinline__ void tma2d(uint32_t smem_dst, const void* map, int cx, int cy, uint32_t bar) {
    asm volatile(
        "cp.async.bulk.tensor.2d.shared::cta.global.tile.mbarrier::complete_tx::bytes "
        "[%0], [%1, {%2, %3}], [%4];"
        :: "r"(smem_dst), "l"(map), "r"(cx), "r"(cy), "r"(bar) : "memory");
}
static __device__ __forceinline__ void ldsm_x4(uint32_t* r, uint32_t addr) {
    asm volatile("ldmatrix.sync.aligned.m8n8.x4.shared.b16 {%0,%1,%2,%3}, [%4];"
                 : "=r"(r[0]), "=r"(r[1]), "=r"(r[2]), "=r"(r[3]) : "r"(addr));
}
static __device__ __forceinline__ void mma_f16(float& d0, float& d1, float& d2, float& d3,
                                               uint32_t a0, uint32_t a1, uint32_t a2, uint32_t a3,
                                               uint32_t b0, uint32_t b1) {
    asm volatile(
        "mma.sync.aligned.m16n8k16.row.col.f32.f16.f16.f32 "
        "{%0,%1,%2,%3}, {%4,%5,%6,%7}, {%8,%9}, {%0,%1,%2,%3};"
        : "+f"(d0), "+f"(d1), "+f"(d2), "+f"(d3)
        : "r"(a0), "r"(a1), "r"(a2), "r"(a3), "r"(b0), "r"(b1));
}
static __device__ __forceinline__ float sigf(float x) {
    x = fminf(fmaxf(x, -30.0f), 30.0f);
    return __fdividef(1.0f, 1.0f + __expf(-x));
}
static __device__ __forceinline__ float tanhfast(float x) {
    x = fminf(fmaxf(x, -15.0f), 15.0f);
    float e = __expf(-2.0f * x);
    return __fdividef(1.0f - e, 1.0f + e);
}

// ---------------- fused prepack kernel ----------------
// blocks [0, PACKA_BLOCKS): pack A' = [fp16(x) | fp16(h)], k-fast
// blocks [PACKA_BLOCKS, ...): transpose w_g[k, j] -> g_W[n'=4j+g, k], fp16
__global__ void pack_all(const float* __restrict__ x, const float* __restrict__ h,
                         const float* __restrict__ w0, const float* __restrict__ w1,
                         const float* __restrict__ w2, const float* __restrict__ w3,
                         const float* __restrict__ w4, const float* __restrict__ w5,
                         const float* __restrict__ w6, const float* __restrict__ w7) {
    int bidx = blockIdx.x;
    int tid = threadIdx.x;
    if (bidx < PACKA_BLOCKS) {
        size_t i8 = (size_t)bidx * 256 + tid;
        size_t idx = i8 * 8;                 // 8 fp16 per thread (16B store)
        int bb = (int)(idx >> 12);
        int k0 = (int)(idx & 4095);
        const float* src = (k0 < HDIM) ? (x + (size_t)bb * HDIM + k0)
                                       : (h + (size_t)bb * HDIM + (k0 - HDIM));
        float4 f0 = *(const float4*)(src);
        float4 f1 = *(const float4*)(src + 4);
        __half2 h0 = __floats2half2_rn(f0.x, f0.y);
        __half2 h1 = __floats2half2_rn(f0.z, f0.w);
        __half2 h2 = __floats2half2_rn(f1.x, f1.y);
        __half2 h3 = __floats2half2_rn(f1.z, f1.w);
        *(uint4*)(g_A + idx) = make_uint4(*(uint32_t*)&h0, *(uint32_t*)&h1,
                                          *(uint32_t*)&h2, *(uint32_t*)&h3);
        return;
    }
    int widx = bidx - PACKA_BLOCKS;
    int z = widx / PACKW_BLOCKS_PER_Z;   // 0..7: z = p*4 + g
    int rem = widx - z * PACKW_BLOCKS_PER_Z;
    int g = z & 3;
    int p = z >> 2;
    const float* src;
    switch (z) {
        case 0: src = w0; break; case 1: src = w1; break;
        case 2: src = w2; break; case 3: src = w3; break;
        case 4: src = w4; break; case 5: src = w5; break;
        case 6: src = w6; break; default: src = w7; break;
    }
    __shared__ float t[32][33];
    int tx = tid & 31, ty = tid >> 5;    // (32, 8)
    int k0 = (rem & 63) * 32, j0 = (rem >> 6) * 32;
#pragma unroll
    for (int rr = 0; rr < 4; rr++) {
        int kk = ty + rr * 8;
        t[kk][tx] = src[(size_t)(k0 + kk) * HDIM + j0 + tx];
    }
    __syncthreads();
#pragma unroll
    for (int rr = 0; rr < 4; rr++) {
        int jj = ty + rr * 8;
        int np = (j0 + jj) * 4 + g;
        g_W[(size_t)np * KTOT + p * HDIM + k0 + tx] = __float2half_rn(t[tx][jj]);
    }
}

// ---------------- fused GEMM + LSTM-cell kernel (ldmatrix + mma.sync fp16) ----------------
__global__ void __launch_bounds__(256, 2) lstm_gemm(
    const __grid_constant__ CUtensorMap mapA,
    const __grid_constant__ CUtensorMap mapW,
    const float* __restrict__ cin,
    const float* __restrict__ bi, const float* __restrict__ bf,
    const float* __restrict__ bo, const float* __restrict__ bg,
    float* __restrict__ out) {
    extern __shared__ char smem[];
    const uint32_t base = smem_u32(smem);
    const int tid = threadIdx.x;
    const int lane = tid & 31, w = tid >> 5;
    const int wm = (w >> 2) * 64;        // warp M offset (2 warps in M, 64 rows each)
    const int wn = (w & 3) * 32;         // warp N offset (4 warps in N, 32 cols each)

    // CTA swizzle: groups of 8 M-tiles x 64 N-tiles (512 CTAs) keep wave footprint in L2
    int bid = blockIdx.x;
    int grp = bid >> 9, rem = bid & 511;
    int m_t = (grp << 3) + (rem & 7);    // 0..31
    int n_t = rem >> 3;                  // 0..63
    const int y0 = m_t * TILE_M, x0 = n_t * TILE_N;

    const uint32_t FULLB = base;         // 3 x 8B
    const uint32_t EMPTB = base + 32;    // 3 x 8B
    float* bias_s = (float*)(smem + 64); // 128 floats
    const uint32_t t0 = (base + 2048 + 1023) & ~1023u;

    if (tid == 0) {
        for (int st = 0; st < STAGES; st++) {
            mbar_init(FULLB + 8 * st, 1);
            mbar_init(EMPTB + 8 * st, 8);
        }
    }
    if (tid < 128) {
        const float* bp[4] = {bi, bf, bo, bg};
        bias_s[tid] = bp[tid & 3][n_t * 32 + (tid >> 2)];
    }
    __syncthreads();

    if (tid == 0) {
        for (int st = 0; st < STAGES; st++) {
            mbar_expect(FULLB + 8 * st, STAGE_BYTES);
            tma2d(t0 + st * STAGE_BYTES, &mapA, st * KC, y0, FULLB + 8 * st);
            tma2d(t0 + st * STAGE_BYTES + A_BYTES, &mapW, st * KC, x0, FULLB + 8 * st);
        }
    }

    float acc[4][4][4];
#pragma unroll
    for (int mt = 0; mt < 4; mt++)
#pragma unroll
        for (int nt = 0; nt < 4; nt++)
#pragma unroll
            for (int q = 0; q < 4; q++) acc[mt][nt][q] = 0.0f;

    // ldmatrix per-lane addressing: mi = matrix index (lane>>3), rr = row (lane&7)
    const int rr = lane & 7, mi = lane >> 3;
    const uint32_t xr = (uint32_t)(rr << 4);
    // A x4: m0 rows0-7/klo, m1 rows8-15/klo, m2 rows0-7/khi, m3 rows8-15/khi
    const uint32_t a_row = (uint32_t)(wm + ((mi & 1) << 3) + rr) * 128;
    // B x4: m0 nlo/klo, m1 nlo/khi, m2 nhi/klo, m3 nhi/khi
    const uint32_t b_row = (uint32_t)(wn + ((mi >> 1) << 3) + rr) * 128;
    uint32_t a_col[4], b_col[4];
#pragma unroll
    for (int g = 0; g < 4; g++) {
        a_col[g] = ((uint32_t)(g * 32 + ((mi >> 1) << 4))) ^ xr;
        b_col[g] = ((uint32_t)(g * 32 + ((mi & 1) << 4))) ^ xr;
    }

    int s = 0, ph = 0;
    for (int i = 0; i < ITERS; i++) {
        mbar_wait(FULLB + 8 * s, ph);
        uint32_t sa = t0 + s * STAGE_BYTES;
        uint32_t sb = sa + A_BYTES;
#pragma unroll
        for (int g = 0; g < 4; g++) {
            uint32_t af[4][4];
#pragma unroll
            for (int mt = 0; mt < 4; mt++)
                ldsm_x4(af[mt], sa + a_row + mt * 2048 + a_col[g]);
            uint32_t bf_[2][4];
#pragma unroll
            for (int p = 0; p < 2; p++)
                ldsm_x4(bf_[p], sb + b_row + p * 2048 + b_col[g]);
#pragma unroll
            for (int mt = 0; mt < 4; mt++)
#pragma unroll
                for (int nt = 0; nt < 4; nt++)
                    mma_f16(acc[mt][nt][0], acc[mt][nt][1], acc[mt][nt][2], acc[mt][nt][3],
                            af[mt][0], af[mt][1], af[mt][2], af[mt][3],
                            bf_[nt >> 1][(nt & 1) * 2], bf_[nt >> 1][(nt & 1) * 2 + 1]);
        }
        if (lane == 0) mbar_arrive(EMPTB + 8 * s);
        if (tid == 0 && i + STAGES < ITERS) {
            mbar_wait_relaxed(EMPTB + 8 * s, ph);
            mbar_expect(FULLB + 8 * s, STAGE_BYTES);
            tma2d(t0 + s * STAGE_BYTES, &mapA, (i + STAGES) * KC, y0, FULLB + 8 * s);
            tma2d(t0 + s * STAGE_BYTES + A_BYTES, &mapW, (i + STAGES) * KC, x0, FULLB + 8 * s);
        }
        if (++s == STAGES) { s = 0; ph ^= 1; }
    }

    // ---------- fused LSTM-cell epilogue ----------
    // thread owns C cols (2c, 2c+1), c = lane&3; gate pair (i,f) on even c, (o,g) on odd c.
    // shfl_xor(1) pairs them; even lane stores h_t, odd lane stores c_t.
    const size_t CELL = (size_t)BDIM * HDIM;
    const int arow = lane >> 2;
#pragma unroll
    for (int mt = 0; mt < 4; mt++) {
#pragma unroll
        for (int nt = 0; nt < 4; nt++) {
            int nloc = wn + nt * 8;
            float bb0 = bias_s[nloc + 2 * (lane & 3)];
            float bb1 = bias_s[nloc + 2 * (lane & 3) + 1];
            int jg = n_t * 32 + (nloc >> 2) + ((lane & 2) >> 1);
#pragma unroll
            for (int hh = 0; hh < 2; hh++) {
                float v0 = acc[mt][nt][hh * 2 + 0] + bb0;
                float v1 = acc[mt][nt][hh * 2 + 1] + bb1;
                float u0 = __shfl_xor_sync(0xffffffffu, v0, 1);
                float u1 = __shfl_xor_sync(0xffffffffu, v1, 1);
                float iv, fv, ov, gv;
                if ((lane & 1) == 0) { iv = v0; fv = v1; ov = u0; gv = u1; }
                else                 { iv = u0; fv = u1; ov = v0; gv = v1; }
                int brow = y0 + wm + mt * 16 + arow + hh * 8;
                size_t off = (size_t)brow * HDIM + jg;
                float cv = __ldg(cin + off);
                float is = sigf(iv), fs = sigf(fv), gt = tanhfast(gv);
                float ct = cv * fs + is * gt;
                if ((lane & 1) == 0) out[off] = sigf(ov) * tanhfast(ct);
                else                 out[CELL + off] = ct;
            }
        }
    }
}

// ---------------- host launch ----------------
typedef CUresult (CUDAAPI* EncFn)(CUtensorMap*, CUtensorMapDataType, cuuint32_t, void*,
                                  const cuuint64_t*, const cuuint64_t*, const cuuint32_t*,
                                  const cuuint32_t*, CUtensorMapInterleave, CUtensorMapSwizzle,
                                  CUtensorMapL2promotion, CUtensorMapFloatOOBfill);

extern "C" void kernel_launch(void* const* d_in, const int* in_sizes, int n_in,
                              void* d_out, int out_size) {
    const float* x = (const float*)d_in[0];
    const float* h = (const float*)d_in[1];
    const float* c = (const float*)d_in[2];
    const float* wx[4] = {(const float*)d_in[3], (const float*)d_in[4],
                          (const float*)d_in[5], (const float*)d_in[6]};
    const float* wh[4] = {(const float*)d_in[7], (const float*)d_in[8],
                          (const float*)d_in[9], (const float*)d_in[10]};
    const float* bi = (const float*)d_in[11];
    const float* bf = (const float*)d_in[12];
    const float* bo = (const float*)d_in[13];
    const float* bg = (const float*)d_in[14];

    void* pA = nullptr; void* pW = nullptr;
    cudaGetSymbolAddress(&pA, g_A);
    cudaGetSymbolAddress(&pW, g_W);

    EncFn enc = nullptr;
    cudaDriverEntryPointQueryResult qres;
    cudaGetDriverEntryPoint("cuTensorMapEncodeTiled", (void**)&enc, cudaEnableDefault, &qres);

    CUtensorMap mA, mW;
    {
        cuuint64_t dims[2] = {KTOT, BDIM};
        cuuint64_t st[1] = {KTOT * sizeof(__half)};
        cuuint32_t box[2] = {KC, TILE_M};
        cuuint32_t es[2] = {1, 1};
        enc(&mA, CU_TENSOR_MAP_DATA_TYPE_FLOAT16, 2, pA, dims, st, box, es,
            CU_TENSOR_MAP_INTERLEAVE_NONE, CU_TENSOR_MAP_SWIZZLE_128B,
            CU_TENSOR_MAP_L2_PROMOTION_L2_128B, CU_TENSOR_MAP_FLOAT_OOB_FILL_NONE);
    }
    {
        cuuint64_t dims[2] = {KTOT, NTOT};
        cuuint64_t st[1] = {KTOT * sizeof(__half)};
        cuuint32_t box[2] = {KC, TILE_N};
        cuuint32_t es[2] = {1, 1};
        enc(&mW, CU_TENSOR_MAP_DATA_TYPE_FLOAT16, 2, pW, dims, st, box, es,
            CU_TENSOR_MAP_INTERLEAVE_NONE, CU_TENSOR_MAP_SWIZZLE_128B,
            CU_TENSOR_MAP_L2_PROMOTION_L2_128B, CU_TENSOR_MAP_FLOAT_OOB_FILL_NONE);
    }

    pack_all<<<PACK_BLOCKS, 256>>>(x, h,
                                   wx[0], wx[1], wx[2], wx[3],
                                   wh[0], wh[1], wh[2], wh[3]);

    cudaFuncSetAttribute(lstm_gemm, cudaFuncAttributeMaxDynamicSharedMemorySize, SMEM_BYTES);
    lstm_gemm<<<(BDIM / TILE_M) * (NTOT / TILE_N), 256, SMEM_BYTES>>>(
        mA, mW, c, bi, bf, bo, bg, (float*)d_out);
}